// round 1
// baseline (speedup 1.0000x reference)
#include <cuda_runtime.h>
#include <math.h>

#define Bb 16
#define Tt 12
#define Nn 300
#define Dd 64
#define T2 10
#define BT (Bb*Tt)        // 192
#define BW (Bb*T2)        // 160
#define NROWS (BW*Nn)     // 48000

// Scratch (static device allocations; no cudaMalloc allowed)
__device__ float g_wf[BT*Nn*Dd];     // gated+normalized features
__device__ float g_P[BT*Dd*Dd];      // per-timestep wf^T feat
__device__ float g_ks[BT*Dd];        // per-timestep column sums of wf
__device__ float g_G[BW*Dd*Dd];      // per-window (sum P) @ w1
__device__ float g_ksum[BW*Dd];      // per-window key sums
__device__ float g_r[NROWS*Dd];      // relu(FFN layer-1) activations

__device__ __forceinline__ void fma4(float4& a, float s, const float4 g) {
    a.x += s*g.x; a.y += s*g.y; a.z += s*g.z; a.w += s*g.w;
}

// ---------------------------------------------------------------------------
// Kernel A: per (b,t): wf = (feat*sigmoid(w)) L2-normalized over D,
//           P = wf^T feat (64x64), ks = column sums of wf.
// grid = 192 blocks, 256 threads. Chunks of 64 rows through smem.
// ---------------------------------------------------------------------------
__global__ __launch_bounds__(256) void kA(const float* __restrict__ feat,
                                          const float* __restrict__ weights) {
    __shared__ float sw[Dd];
    __shared__ float fs[64][Dd];
    __shared__ float ws[64][Dd];
    const int bt  = blockIdx.x;
    const int tid = threadIdx.x;
    if (tid < Dd) sw[tid] = 1.0f / (1.0f + expf(-weights[tid]));

    float acc[4][4];
    #pragma unroll
    for (int i = 0; i < 4; ++i)
        #pragma unroll
        for (int j = 0; j < 4; ++j) acc[i][j] = 0.0f;
    float ksa[4] = {0.f, 0.f, 0.f, 0.f};

    const int ty = tid >> 4;        // j-tile (0..15)
    const int tx = tid & 15;        // d-tile (0..15)
    const float* fbase = feat + (size_t)bt * Nn * Dd;
    float* wbase = g_wf + (size_t)bt * Nn * Dd;
    __syncthreads();

    for (int c = 0; c < 5; ++c) {
        const int r0 = c * 64;
        const int nr = min(64, Nn - r0);
        const int nv = nr * 16;     // float4 count
        for (int i = tid; i < nv; i += 256)
            ((float4*)fs)[i] = ((const float4*)(fbase + (size_t)r0 * Dd))[i];
        __syncthreads();

        // L2 norm: 4 threads per row
        {
            const int row = tid >> 2, part = tid & 3;
            float s = 0.0f;
            if (row < nr) {
                #pragma unroll
                for (int k = 0; k < 16; ++k) {
                    float v = fs[row][part*16 + k] * sw[part*16 + k];
                    s += v * v;
                }
            }
            s += __shfl_xor_sync(0xffffffffu, s, 1);
            s += __shfl_xor_sync(0xffffffffu, s, 2);
            if (row < nr) {
                float scale = 1.0f / fmaxf(sqrtf(s), 1e-12f);
                #pragma unroll
                for (int k = 0; k < 16; ++k)
                    ws[row][part*16 + k] = fs[row][part*16 + k] * sw[part*16 + k] * scale;
            }
        }
        __syncthreads();

        // store wf chunk to global
        for (int i = tid; i < nv; i += 256)
            ((float4*)(wbase + (size_t)r0 * Dd))[i] = ((const float4*)ws)[i];

        // P outer-product accumulation: each thread owns a 4x4 tile
        for (int n = 0; n < nr; ++n) {
            const float4 w4 = *(const float4*)&ws[n][ty*4];
            const float4 f4 = *(const float4*)&fs[n][tx*4];
            const float wv[4] = {w4.x, w4.y, w4.z, w4.w};
            const float fv[4] = {f4.x, f4.y, f4.z, f4.w};
            #pragma unroll
            for (int jj = 0; jj < 4; ++jj)
                #pragma unroll
                for (int dd = 0; dd < 4; ++dd)
                    acc[jj][dd] += wv[jj] * fv[dd];
            if (tx == 0) {
                ksa[0] += w4.x; ksa[1] += w4.y; ksa[2] += w4.z; ksa[3] += w4.w;
            }
        }
        __syncthreads();
    }

    float* Pb = g_P + (size_t)bt * Dd * Dd;
    #pragma unroll
    for (int jj = 0; jj < 4; ++jj)
        #pragma unroll
        for (int dd = 0; dd < 4; ++dd)
            Pb[(ty*4 + jj)*Dd + tx*4 + dd] = acc[jj][dd];
    if (tx == 0) {
        #pragma unroll
        for (int jj = 0; jj < 4; ++jj)
            g_ks[bt*Dd + ty*4 + jj] = ksa[jj];
    }
}

// ---------------------------------------------------------------------------
// Kernel B: per window (b,t2): M = P[t2]+P[t2+1]+P[t2+2]; G = M @ w1;
//           ksum = ks[t2]+ks[t2+1]+ks[t2+2].
// grid = 160 blocks, 256 threads.
// ---------------------------------------------------------------------------
__global__ __launch_bounds__(256) void kB(const float* __restrict__ w1) {
    __shared__ float Ms[Dd*Dd];
    __shared__ float w1s[Dd*Dd];
    const int bw  = blockIdx.x;
    const int b   = bw / T2;
    const int t2  = bw % T2;
    const int bt0 = b * Tt + t2;
    const float* P0 = g_P + (size_t)bt0 * Dd * Dd;
    const int tid = threadIdx.x;

    for (int i = tid; i < 1024; i += 256) {
        float4 a = ((const float4*)P0)[i];
        float4 c = ((const float4*)(P0 + Dd*Dd))[i];
        float4 d = ((const float4*)(P0 + 2*Dd*Dd))[i];
        float4 m;
        m.x = a.x + c.x + d.x; m.y = a.y + c.y + d.y;
        m.z = a.z + c.z + d.z; m.w = a.w + c.w + d.w;
        ((float4*)Ms)[i] = m;
        ((float4*)w1s)[i] = ((const float4*)w1)[i];
    }
    if (tid < Dd) {
        g_ksum[bw*Dd + tid] = g_ks[bt0*Dd + tid]
                            + g_ks[(bt0+1)*Dd + tid]
                            + g_ks[(bt0+2)*Dd + tid];
    }
    __syncthreads();

    const int d  = tid & 63;
    const int jg = tid >> 6;   // 0..3, each handles 16 j's
    float* Gb = g_G + (size_t)bw * Dd * Dd;
    for (int j = jg*16; j < jg*16 + 16; ++j) {
        float s = 0.0f;
        #pragma unroll 16
        for (int k = 0; k < 64; ++k)
            s += Ms[j*64 + k] * w1s[k*64 + d];
        Gb[j*64 + d] = s;
    }
}

// ---------------------------------------------------------------------------
// Kernel C1: per row n of window (b,t2): q = wf[b,t2+2,n];
//            deg = q . ksum; r = relu(q@G / deg + b1)  -> g_r
// grid = 160 blocks, 320 threads (300 active rows).
// ---------------------------------------------------------------------------
__global__ __launch_bounds__(320) void kC1(const float* __restrict__ b1) {
    __shared__ float Gs[Dd*Dd];
    __shared__ float kss[Dd];
    __shared__ float b1s[Dd];
    const int bw  = blockIdx.x;
    const int tid = threadIdx.x;
    const float* Gb = g_G + (size_t)bw * Dd * Dd;
    for (int i = tid; i < 1024; i += 320)
        ((float4*)Gs)[i] = ((const float4*)Gb)[i];
    if (tid < Dd) { kss[tid] = g_ksum[bw*Dd + tid]; b1s[tid] = b1[tid]; }
    __syncthreads();
    if (tid >= Nn) return;

    const int b  = bw / T2;
    const int t2 = bw % T2;
    const float4* qp = (const float4*)(g_wf +
        ((size_t)((b*Tt + t2 + 2)*Nn) + tid) * Dd);

    float4 u[16];
    #pragma unroll
    for (int i = 0; i < 16; ++i) u[i] = make_float4(0.f, 0.f, 0.f, 0.f);
    float dg = 0.0f;

    float4 qv = qp[0];
    for (int jg = 0; jg < 16; ++jg) {
        const float4 qn = (jg < 15) ? qp[jg + 1] : qv;  // prefetch
        const int j0 = jg * 4;
        dg += qv.x*kss[j0] + qv.y*kss[j0+1] + qv.z*kss[j0+2] + qv.w*kss[j0+3];
        const float4* g0 = (const float4*)&Gs[j0 * 64];
        #pragma unroll
        for (int dd = 0; dd < 16; ++dd) {
            fma4(u[dd], qv.x, g0[dd]);
            fma4(u[dd], qv.y, g0[16 + dd]);
            fma4(u[dd], qv.z, g0[32 + dd]);
            fma4(u[dd], qv.w, g0[48 + dd]);
        }
        qv = qn;
    }

    const float dinv = (dg == 0.0f) ? 0.0f : 1.0f / dg;
    float4* rp = (float4*)(g_r + ((size_t)bw * Nn + tid) * Dd);
    #pragma unroll
    for (int dd = 0; dd < 16; ++dd) {
        float4 v;
        v.x = fmaxf(u[dd].x * dinv + b1s[dd*4 + 0], 0.0f);
        v.y = fmaxf(u[dd].y * dinv + b1s[dd*4 + 1], 0.0f);
        v.z = fmaxf(u[dd].z * dinv + b1s[dd*4 + 2], 0.0f);
        v.w = fmaxf(u[dd].w * dinv + b1s[dd*4 + 3], 0.0f);
        rp[dd] = v;
    }
}

// ---------------------------------------------------------------------------
// Kernel C2: per row: h = r@w2 + b2; s = feat + h; LayerNorm -> out.
// grid = ceil(48000/256), 256 threads.
// ---------------------------------------------------------------------------
__global__ __launch_bounds__(256) void kC2(const float* __restrict__ feat,
                                           const float* __restrict__ w2,
                                           const float* __restrict__ b2,
                                           const float* __restrict__ gamma,
                                           const float* __restrict__ beta,
                                           float* __restrict__ out) {
    __shared__ float w2s[Dd*Dd];
    __shared__ float b2s[Dd], gs[Dd], bs[Dd];
    const int tid = threadIdx.x;
    for (int i = tid; i < 1024; i += 256)
        ((float4*)w2s)[i] = ((const float4*)w2)[i];
    if (tid < Dd) { b2s[tid] = b2[tid]; gs[tid] = gamma[tid]; bs[tid] = beta[tid]; }
    __syncthreads();

    const int row = blockIdx.x * 256 + tid;
    if (row >= NROWS) return;

    const float4* rp = (const float4*)(g_r + (size_t)row * Dd);
    float4 h[16];
    #pragma unroll
    for (int i = 0; i < 16; ++i) h[i] = make_float4(0.f, 0.f, 0.f, 0.f);

    float4 rv = rp[0];
    for (int kg = 0; kg < 16; ++kg) {
        const float4 rn = (kg < 15) ? rp[kg + 1] : rv;  // prefetch
        const float4* wr = (const float4*)&w2s[kg * 4 * 64];
        #pragma unroll
        for (int dd = 0; dd < 16; ++dd) {
            fma4(h[dd], rv.x, wr[dd]);
            fma4(h[dd], rv.y, wr[16 + dd]);
            fma4(h[dd], rv.z, wr[32 + dd]);
            fma4(h[dd], rv.w, wr[48 + dd]);
        }
        rv = rn;
    }

    const int b   = row / (T2 * Nn);
    const int rem = row % (T2 * Nn);
    const int t2  = rem / Nn;
    const int n   = rem % Nn;
    const float4* fp = (const float4*)(feat +
        ((size_t)((b*Tt + t2 + 2)*Nn) + n) * Dd);

    float sum = 0.0f;
    #pragma unroll
    for (int dd = 0; dd < 16; ++dd) {
        const float4 f = fp[dd];
        h[dd].x += f.x + b2s[dd*4 + 0];
        h[dd].y += f.y + b2s[dd*4 + 1];
        h[dd].z += f.z + b2s[dd*4 + 2];
        h[dd].w += f.w + b2s[dd*4 + 3];
        sum += h[dd].x + h[dd].y + h[dd].z + h[dd].w;
    }
    const float mu = sum * (1.0f / 64.0f);
    float vs = 0.0f;
    #pragma unroll
    for (int dd = 0; dd < 16; ++dd) {
        float a;
        a = h[dd].x - mu; vs += a * a;
        a = h[dd].y - mu; vs += a * a;
        a = h[dd].z - mu; vs += a * a;
        a = h[dd].w - mu; vs += a * a;
    }
    const float rstd = rsqrtf(vs * (1.0f / 64.0f) + 1e-5f);

    float4* op = (float4*)(out + (size_t)row * Dd);
    #pragma unroll
    for (int dd = 0; dd < 16; ++dd) {
        float4 o;
        o.x = (h[dd].x - mu) * rstd * gs[dd*4 + 0] + bs[dd*4 + 0];
        o.y = (h[dd].y - mu) * rstd * gs[dd*4 + 1] + bs[dd*4 + 1];
        o.z = (h[dd].z - mu) * rstd * gs[dd*4 + 2] + bs[dd*4 + 2];
        o.w = (h[dd].w - mu) * rstd * gs[dd*4 + 3] + bs[dd*4 + 3];
        op[dd] = o;
    }
}

extern "C" void kernel_launch(void* const* d_in, const int* in_sizes, int n_in,
                              void* d_out, int out_size) {
    const float* feat    = (const float*)d_in[0];
    const float* weights = (const float*)d_in[1];
    const float* w1      = (const float*)d_in[2];
    const float* b1      = (const float*)d_in[3];
    const float* w2      = (const float*)d_in[4];
    const float* b2      = (const float*)d_in[5];
    const float* gamma   = (const float*)d_in[6];
    const float* beta    = (const float*)d_in[7];
    float* out = (float*)d_out;

    kA<<<BT, 256>>>(feat, weights);
    kB<<<BW, 256>>>(w1);
    kC1<<<BW, 320>>>(b1);
    kC2<<<(NROWS + 255) / 256, 256>>>(feat, w2, b2, gamma, beta, out);
}

// round 2
// speedup vs baseline: 1.4070x; 1.4070x over previous
#include <cuda_runtime.h>
#include <math.h>

#define Bb 16
#define Tt 12
#define Nn 300
#define Dd 64
#define T2 10
#define BT (Bb*Tt)        // 192
#define BW (Bb*T2)        // 160
#define NROWS (BW*Nn)     // 48000
#define QPAD 68           // padded row stride for transposed tiles

// Scratch (static device allocations; no cudaMalloc allowed)
__device__ float g_wf[BT*Nn*Dd];       // gated+normalized features
__device__ float g_P5[BT*5*Dd*Dd];     // per-(timestep,chunk) partial wf^T feat
__device__ float g_ks5[BT*5*Dd];       // per-(timestep,chunk) partial column sums
__device__ float g_G[BW*Dd*Dd];        // per-window (sum P) @ w1
__device__ float g_ksum[BW*Dd];        // per-window key sums

// ---------------------------------------------------------------------------
// Kernel A: per (bt, chunk): gate+L2-normalize 64 rows, write wf,
//           accumulate partial P (64x64 outer product) and partial ks.
// grid = 960 blocks, 256 threads.
// ---------------------------------------------------------------------------
__global__ __launch_bounds__(256) void kA(const float* __restrict__ feat,
                                          const float* __restrict__ weights) {
    __shared__ float sw[Dd];
    __shared__ float fs[64][Dd];
    __shared__ float ws[64][Dd];
    const int blk = blockIdx.x;
    const int bt  = blk / 5;
    const int c   = blk % 5;
    const int r0  = c * 64;
    const int nr  = min(64, Nn - r0);     // 64 or 44
    const int tid = threadIdx.x;
    if (tid < Dd) sw[tid] = 1.0f / (1.0f + expf(-weights[tid]));

    const float* fbase = feat + ((size_t)bt * Nn + r0) * Dd;
    const int nv = nr * 16;
    for (int i = tid; i < nv; i += 256)
        ((float4*)fs)[i] = ((const float4*)fbase)[i];
    __syncthreads();

    // L2 norm: 4 threads per row
    {
        const int row = tid >> 2, part = tid & 3;
        float s = 0.0f;
        if (row < nr) {
            #pragma unroll
            for (int k = 0; k < 16; ++k) {
                float v = fs[row][part*16 + k] * sw[part*16 + k];
                s += v * v;
            }
        }
        s += __shfl_xor_sync(0xffffffffu, s, 1);
        s += __shfl_xor_sync(0xffffffffu, s, 2);
        if (row < nr) {
            float scale = 1.0f / fmaxf(sqrtf(s), 1e-12f);
            #pragma unroll
            for (int k = 0; k < 16; ++k)
                ws[row][part*16 + k] = fs[row][part*16 + k] * sw[part*16 + k] * scale;
        }
    }
    __syncthreads();

    // store wf chunk
    float* wbase = g_wf + ((size_t)bt * Nn + r0) * Dd;
    for (int i = tid; i < nv; i += 256)
        ((float4*)wbase)[i] = ((const float4*)ws)[i];

    // partial P: each thread owns a 4x4 tile
    const int ty = tid >> 4;
    const int tx = tid & 15;
    float acc[4][4];
    #pragma unroll
    for (int i = 0; i < 4; ++i)
        #pragma unroll
        for (int j = 0; j < 4; ++j) acc[i][j] = 0.0f;
    float ksa[4] = {0.f, 0.f, 0.f, 0.f};

    for (int n = 0; n < nr; ++n) {
        const float4 w4 = *(const float4*)&ws[n][ty*4];
        const float4 f4 = *(const float4*)&fs[n][tx*4];
        const float wv[4] = {w4.x, w4.y, w4.z, w4.w};
        const float fv[4] = {f4.x, f4.y, f4.z, f4.w};
        #pragma unroll
        for (int jj = 0; jj < 4; ++jj)
            #pragma unroll
            for (int dd = 0; dd < 4; ++dd)
                acc[jj][dd] += wv[jj] * fv[dd];
        if (tx == 0) {
            ksa[0] += w4.x; ksa[1] += w4.y; ksa[2] += w4.z; ksa[3] += w4.w;
        }
    }

    float* Pb = g_P5 + (size_t)blk * Dd * Dd;
    #pragma unroll
    for (int jj = 0; jj < 4; ++jj)
        *(float4*)&Pb[(ty*4 + jj)*Dd + tx*4] =
            make_float4(acc[jj][0], acc[jj][1], acc[jj][2], acc[jj][3]);
    if (tx == 0) {
        #pragma unroll
        for (int jj = 0; jj < 4; ++jj)
            g_ks5[blk*Dd + ty*4 + jj] = ksa[jj];
    }
}

// ---------------------------------------------------------------------------
// Kernel B: per window: M = sum of 15 partial P slices; G = M @ w1;
//           ksum = sum of 15 partial ks. grid = 160, 256 threads.
// ---------------------------------------------------------------------------
__global__ __launch_bounds__(256) void kB(const float* __restrict__ w1) {
    __shared__ float Ms[Dd*Dd];
    __shared__ float w1s[Dd*Dd];
    const int bw  = blockIdx.x;
    const int b   = bw / T2;
    const int t2  = bw % T2;
    const int bt0 = b * Tt + t2;
    const int tid = threadIdx.x;

    for (int i = tid; i < 1024; i += 256) {
        float4 m = make_float4(0.f, 0.f, 0.f, 0.f);
        #pragma unroll
        for (int s = 0; s < 3; ++s)
            #pragma unroll
            for (int cc = 0; cc < 5; ++cc) {
                const float4 v = ((const float4*)(g_P5 +
                    (size_t)((bt0 + s)*5 + cc) * Dd * Dd))[i];
                m.x += v.x; m.y += v.y; m.z += v.z; m.w += v.w;
            }
        ((float4*)Ms)[i]  = m;
        ((float4*)w1s)[i] = ((const float4*)w1)[i];
    }
    if (tid < Dd) {
        float s = 0.0f;
        #pragma unroll
        for (int sl = 0; sl < 15; ++sl)
            s += g_ks5[((bt0 + sl/5)*5 + sl%5)*Dd + tid];
        g_ksum[bw*Dd + tid] = s;
    }
    __syncthreads();

    const int d  = tid & 63;
    const int jg = tid >> 6;
    float* Gb = g_G + (size_t)bw * Dd * Dd;
    for (int j = jg*16; j < jg*16 + 16; ++j) {
        float s = 0.0f;
        #pragma unroll 16
        for (int k = 0; k < 64; ++k)
            s += Ms[j*64 + k] * w1s[k*64 + d];
        Gb[j*64 + d] = s;
    }
}

// ---------------------------------------------------------------------------
// Kernel C (fused C1+C2): per (window, 64-row tile):
//   u = q @ G; r = relu(u/deg + b1); h = r @ w2 + b2; s = feat + h; LayerNorm.
// Tiled GEMM: thread = 4x4 tile. grid = 800 blocks, 256 threads.
// ---------------------------------------------------------------------------
__global__ __launch_bounds__(256) void kC(const float* __restrict__ feat,
                                          const float* __restrict__ b1,
                                          const float* __restrict__ w2,
                                          const float* __restrict__ b2,
                                          const float* __restrict__ gamma,
                                          const float* __restrict__ beta,
                                          float* __restrict__ out) {
    __shared__ float Gs[Dd*Dd];      // G, later reused for w2
    __shared__ float QR[Dd*QPAD];    // Q^T, later reused for R^T
    __shared__ float kss[Dd], b1s[Dd], b2s[Dd], gms[Dd], bts[Dd], degs[64];

    const int blk  = blockIdx.x;
    const int bw   = blk / 5;
    const int tile = blk % 5;
    const int r0   = tile * 64;
    const int nr   = min(64, Nn - r0);
    const int b    = bw / T2;
    const int t2   = bw % T2;
    const int tid  = threadIdx.x;
    const int ty   = tid >> 4;       // row group 0..15
    const int tx   = tid & 15;       // col group 0..15

    // stage Q^T (zero-fill invalid rows), G, small vectors
    {
        const float4* qb = (const float4*)(g_wf +
            ((size_t)((b*Tt + t2 + 2)*Nn) + r0) * Dd);
        for (int idx = tid; idx < 1024; idx += 256) {
            const int row = idx >> 4, c4 = idx & 15;
            float4 v = make_float4(0.f, 0.f, 0.f, 0.f);
            if (row < nr) v = qb[row*16 + c4];
            QR[(c4*4 + 0)*QPAD + row] = v.x;
            QR[(c4*4 + 1)*QPAD + row] = v.y;
            QR[(c4*4 + 2)*QPAD + row] = v.z;
            QR[(c4*4 + 3)*QPAD + row] = v.w;
        }
        const float4* Gb = (const float4*)(g_G + (size_t)bw * Dd * Dd);
        for (int i = tid; i < 1024; i += 256)
            ((float4*)Gs)[i] = Gb[i];
        if (tid < Dd) {
            kss[tid] = g_ksum[bw*Dd + tid];
            b1s[tid] = b1[tid]; b2s[tid] = b2[tid];
            gms[tid] = gamma[tid]; bts[tid] = beta[tid];
        }
    }
    __syncthreads();

    // deg per row (threads 0..63)
    if (tid < 64) {
        float s = 0.0f;
        #pragma unroll 16
        for (int k = 0; k < 64; ++k)
            s += QR[k*QPAD + tid] * kss[k];
        degs[tid] = (s == 0.0f) ? 0.0f : 1.0f / s;
    }
    __syncthreads();

    // GEMM1: u = Q @ G
    float acc[4][4];
    #pragma unroll
    for (int i = 0; i < 4; ++i)
        #pragma unroll
        for (int j = 0; j < 4; ++j) acc[i][j] = 0.0f;

    #pragma unroll 8
    for (int k = 0; k < 64; ++k) {
        const float4 a4 = *(const float4*)&QR[k*QPAD + ty*4];
        const float4 b4 = *(const float4*)&Gs[k*Dd + tx*4];
        const float av[4] = {a4.x, a4.y, a4.z, a4.w};
        const float bv[4] = {b4.x, b4.y, b4.z, b4.w};
        #pragma unroll
        for (int i = 0; i < 4; ++i)
            #pragma unroll
            for (int j = 0; j < 4; ++j)
                acc[i][j] += av[i] * bv[j];
    }

    // relu(u/deg + b1) -> registers
    float r[4][4];
    #pragma unroll
    for (int i = 0; i < 4; ++i) {
        const float dinv = degs[ty*4 + i];
        #pragma unroll
        for (int j = 0; j < 4; ++j)
            r[i][j] = fmaxf(acc[i][j] * dinv + b1s[tx*4 + j], 0.0f);
    }
    __syncthreads();   // everyone done reading QR/Gs

    // store R^T into QR, load w2 into Gs
    #pragma unroll
    for (int i = 0; i < 4; ++i)
        #pragma unroll
        for (int j = 0; j < 4; ++j)
            QR[(tx*4 + j)*QPAD + ty*4 + i] = r[i][j];
    {
        const float4* w2b = (const float4*)w2;
        for (int i = tid; i < 1024; i += 256)
            ((float4*)Gs)[i] = w2b[i];
    }
    __syncthreads();

    // GEMM2: h = R @ w2
    #pragma unroll
    for (int i = 0; i < 4; ++i)
        #pragma unroll
        for (int j = 0; j < 4; ++j) acc[i][j] = 0.0f;

    #pragma unroll 8
    for (int k = 0; k < 64; ++k) {
        const float4 a4 = *(const float4*)&QR[k*QPAD + ty*4];
        const float4 b4 = *(const float4*)&Gs[k*Dd + tx*4];
        const float av[4] = {a4.x, a4.y, a4.z, a4.w};
        const float bv[4] = {b4.x, b4.y, b4.z, b4.w};
        #pragma unroll
        for (int i = 0; i < 4; ++i)
            #pragma unroll
            for (int j = 0; j < 4; ++j)
                acc[i][j] += av[i] * bv[j];
    }

    // epilogue: residual + bias, LayerNorm per row (16 threads per row, width-16 shfl)
    const float* fb = feat + ((size_t)((b*Tt + t2 + 2)*Nn) + r0) * Dd;
    float* ob = out + ((size_t)bw * Nn + r0) * Dd;
    #pragma unroll
    for (int i = 0; i < 4; ++i) {
        const int row = ty*4 + i;
        const bool valid = row < nr;
        float4 f4 = make_float4(0.f, 0.f, 0.f, 0.f);
        if (valid) f4 = ((const float4*)fb)[row*16 + tx];
        float h0 = acc[i][0] + f4.x + b2s[tx*4 + 0];
        float h1 = acc[i][1] + f4.y + b2s[tx*4 + 1];
        float h2 = acc[i][2] + f4.z + b2s[tx*4 + 2];
        float h3 = acc[i][3] + f4.w + b2s[tx*4 + 3];

        float s = h0 + h1 + h2 + h3;
        #pragma unroll
        for (int m = 1; m < 16; m <<= 1)
            s += __shfl_xor_sync(0xffffffffu, s, m, 16);
        const float mu = s * (1.0f / 64.0f);

        float a0 = h0 - mu, a1 = h1 - mu, a2 = h2 - mu, a3 = h3 - mu;
        float vs = a0*a0 + a1*a1 + a2*a2 + a3*a3;
        #pragma unroll
        for (int m = 1; m < 16; m <<= 1)
            vs += __shfl_xor_sync(0xffffffffu, vs, m, 16);
        const float rstd = rsqrtf(vs * (1.0f / 64.0f) + 1e-5f);

        if (valid) {
            float4 o;
            o.x = a0 * rstd * gms[tx*4 + 0] + bts[tx*4 + 0];
            o.y = a1 * rstd * gms[tx*4 + 1] + bts[tx*4 + 1];
            o.z = a2 * rstd * gms[tx*4 + 2] + bts[tx*4 + 2];
            o.w = a3 * rstd * gms[tx*4 + 3] + bts[tx*4 + 3];
            ((float4*)ob)[row*16 + tx] = o;
        }
    }
}

extern "C" void kernel_launch(void* const* d_in, const int* in_sizes, int n_in,
                              void* d_out, int out_size) {
    const float* feat    = (const float*)d_in[0];
    const float* weights = (const float*)d_in[1];
    const float* w1      = (const float*)d_in[2];
    const float* b1      = (const float*)d_in[3];
    const float* w2      = (const float*)d_in[4];
    const float* b2      = (const float*)d_in[5];
    const float* gamma   = (const float*)d_in[6];
    const float* beta    = (const float*)d_in[7];
    float* out = (float*)d_out;

    kA<<<BT*5, 256>>>(feat, weights);
    kB<<<BW, 256>>>(w1);
    kC<<<BW*5, 256>>>(feat, b1, w2, b2, gamma, beta, out);
}

// round 3
// speedup vs baseline: 1.5818x; 1.1242x over previous
#include <cuda_runtime.h>
#include <math.h>

#define Bb 16
#define Tt 12
#define Nn 300
#define Dd 64
#define T2 10
#define BT (Bb*Tt)        // 192
#define BW (Bb*T2)        // 160
#define QPAD 68           // padded row stride for transposed tiles

// Scratch (static device allocations; no cudaMalloc allowed)
__device__ float g_S5[BT*5*Dd*Dd];     // partial S = sum_n scale_n f f^T per (bt,chunk)
__device__ float g_ss5[BT*5*Dd];       // partial ss = sum_n scale_n f[n,:]
__device__ float g_G[BW*Dd*Dd];        // per-window diag(sw^2) S_win w1
__device__ float g_v[BW*Dd];           // per-window sw^2 * ss_win

// ---------------------------------------------------------------------------
// Kernel A: per (bt, chunk of 64 rows): compute per-row scale
//   scale_n = 1/max(||f_n .* sw||, 1e-12), accumulate partial
//   S[j,d] = sum_n scale_n f[n,j] f[n,d]  and  ss[j] = sum_n scale_n f[n,j].
// grid = 960 blocks, 256 threads. No wf materialization.
// ---------------------------------------------------------------------------
__global__ __launch_bounds__(256) void kA(const float* __restrict__ feat,
                                          const float* __restrict__ weights) {
    __shared__ float sw[Dd];
    __shared__ float fs[64][Dd];
    __shared__ float scs[64];
    const int blk = blockIdx.x;
    const int bt  = blk / 5;
    const int c   = blk % 5;
    const int r0  = c * 64;
    const int nr  = min(64, Nn - r0);     // 64 or 44
    const int tid = threadIdx.x;
    if (tid < Dd) sw[tid] = 1.0f / (1.0f + expf(-weights[tid]));

    const float* fbase = feat + ((size_t)bt * Nn + r0) * Dd;
    const int nv = nr * 16;
    for (int i = tid; i < nv; i += 256)
        ((float4*)fs)[i] = ((const float4*)fbase)[i];
    __syncthreads();

    // per-row scale: 4 threads per row
    {
        const int row = tid >> 2, part = tid & 3;
        float s = 0.0f;
        if (row < 64) {
            #pragma unroll
            for (int k = 0; k < 16; ++k) {
                float v = (row < nr) ? fs[row][part*16 + k] * sw[part*16 + k] : 0.0f;
                s += v * v;
            }
        }
        s += __shfl_xor_sync(0xffffffffu, s, 1);
        s += __shfl_xor_sync(0xffffffffu, s, 2);
        if (part == 0 && row < 64)
            scs[row] = (row < nr) ? 1.0f / fmaxf(sqrtf(s), 1e-12f) : 0.0f;
        // zero-pad invalid rows so the MAC loop can run a fixed 64 iters
        if (row >= nr && row < 64) {
            #pragma unroll
            for (int k = 0; k < 16; ++k) fs[row][part*16 + k] = 0.0f;
        }
    }
    __syncthreads();

    // partial S: each thread owns a 4x4 tile; scale folded into j-side
    const int ty = tid >> 4;
    const int tx = tid & 15;
    float acc[4][4];
    #pragma unroll
    for (int i = 0; i < 4; ++i)
        #pragma unroll
        for (int j = 0; j < 4; ++j) acc[i][j] = 0.0f;
    float ksa[4] = {0.f, 0.f, 0.f, 0.f};

    #pragma unroll 4
    for (int n = 0; n < 64; ++n) {
        const float  sc = scs[n];
        const float4 w4 = *(const float4*)&fs[n][ty*4];
        const float4 f4 = *(const float4*)&fs[n][tx*4];
        const float sv[4] = {sc*w4.x, sc*w4.y, sc*w4.z, sc*w4.w};
        const float fv[4] = {f4.x, f4.y, f4.z, f4.w};
        #pragma unroll
        for (int jj = 0; jj < 4; ++jj)
            #pragma unroll
            for (int dd = 0; dd < 4; ++dd)
                acc[jj][dd] += sv[jj] * fv[dd];
        if (tx == 0) {
            ksa[0] += sv[0]; ksa[1] += sv[1]; ksa[2] += sv[2]; ksa[3] += sv[3];
        }
    }

    float* Sb = g_S5 + (size_t)blk * Dd * Dd;
    #pragma unroll
    for (int jj = 0; jj < 4; ++jj)
        *(float4*)&Sb[(ty*4 + jj)*Dd + tx*4] =
            make_float4(acc[jj][0], acc[jj][1], acc[jj][2], acc[jj][3]);
    if (tx == 0) {
        #pragma unroll
        for (int jj = 0; jj < 4; ++jj)
            g_ss5[blk*Dd + ty*4 + jj] = ksa[jj];
    }
}

// ---------------------------------------------------------------------------
// Kernel B: per window: Ms[j,:] = sw2[j] * sum of 15 partial S slices;
//   G = Ms @ w1;  v[j] = sw2[j] * sum of 15 partial ss.
// grid = 160, 256 threads.
// ---------------------------------------------------------------------------
__global__ __launch_bounds__(256) void kB(const float* __restrict__ w1,
                                          const float* __restrict__ weights) {
    __shared__ float Ms[Dd*Dd];
    __shared__ float w1s[Dd*Dd];
    __shared__ float sw2[Dd];
    const int bw  = blockIdx.x;
    const int b   = bw / T2;
    const int t2  = bw % T2;
    const int bt0 = b * Tt + t2;
    const int tid = threadIdx.x;

    if (tid < Dd) {
        float s = 1.0f / (1.0f + expf(-weights[tid]));
        sw2[tid] = s * s;
    }
    __syncthreads();

    for (int i = tid; i < 1024; i += 256) {
        float4 m = make_float4(0.f, 0.f, 0.f, 0.f);
        #pragma unroll
        for (int s = 0; s < 3; ++s)
            #pragma unroll
            for (int cc = 0; cc < 5; ++cc) {
                const float4 v = ((const float4*)(g_S5 +
                    (size_t)((bt0 + s)*5 + cc) * Dd * Dd))[i];
                m.x += v.x; m.y += v.y; m.z += v.z; m.w += v.w;
            }
        const float s2 = sw2[i >> 4];   // row = i/16
        m.x *= s2; m.y *= s2; m.z *= s2; m.w *= s2;
        ((float4*)Ms)[i]  = m;
        ((float4*)w1s)[i] = ((const float4*)w1)[i];
    }
    if (tid < Dd) {
        float s = 0.0f;
        #pragma unroll
        for (int sl = 0; sl < 15; ++sl)
            s += g_ss5[((bt0 + sl/5)*5 + sl%5)*Dd + tid];
        g_v[bw*Dd + tid] = sw2[tid] * s;
    }
    __syncthreads();

    const int d  = tid & 63;
    const int jg = tid >> 6;
    float* Gb = g_G + (size_t)bw * Dd * Dd;
    for (int j = jg*16; j < jg*16 + 16; ++j) {
        float s = 0.0f;
        #pragma unroll 16
        for (int k = 0; k < 64; ++k)
            s += Ms[j*64 + k] * w1s[k*64 + d];
        Gb[j*64 + d] = s;
    }
}

// ---------------------------------------------------------------------------
// Kernel C: per (window, 64-row tile): F = feat rows (current timestep);
//   u = F @ G; deg = F @ v; r = relu(u/deg + b1); h = r @ w2 + b2;
//   s = F + h; LayerNorm -> out.  Thread = 4x4 tile. grid = 800, 256 thr.
// ---------------------------------------------------------------------------
__global__ __launch_bounds__(256) void kC(const float* __restrict__ feat,
                                          const float* __restrict__ b1,
                                          const float* __restrict__ w2,
                                          const float* __restrict__ b2,
                                          const float* __restrict__ gamma,
                                          const float* __restrict__ beta,
                                          float* __restrict__ out) {
    __shared__ float Gs[Dd*Dd];      // G, later reused for w2
    __shared__ float QR[Dd*QPAD];    // F^T, later reused for R^T
    __shared__ float kss[Dd], b1s[Dd], b2s[Dd], gms[Dd], bts[Dd], degs[64];

    const int blk  = blockIdx.x;
    const int bw   = blk / 5;
    const int tile = blk % 5;
    const int r0   = tile * 64;
    const int nr   = min(64, Nn - r0);
    const int b    = bw / T2;
    const int t2   = bw % T2;
    const int tid  = threadIdx.x;
    const int ty   = tid >> 4;       // row group 0..15
    const int tx   = tid & 15;       // col group 0..15

    const float* fb = feat + ((size_t)((b*Tt + t2 + 2)*Nn) + r0) * Dd;

    // stage F^T (zero-fill invalid rows), G, small vectors
    {
        const float4* qb = (const float4*)fb;
        for (int idx = tid; idx < 1024; idx += 256) {
            const int row = idx >> 4, c4 = idx & 15;
            float4 v = make_float4(0.f, 0.f, 0.f, 0.f);
            if (row < nr) v = qb[row*16 + c4];
            QR[(c4*4 + 0)*QPAD + row] = v.x;
            QR[(c4*4 + 1)*QPAD + row] = v.y;
            QR[(c4*4 + 2)*QPAD + row] = v.z;
            QR[(c4*4 + 3)*QPAD + row] = v.w;
        }
        const float4* Gb = (const float4*)(g_G + (size_t)bw * Dd * Dd);
        for (int i = tid; i < 1024; i += 256)
            ((float4*)Gs)[i] = Gb[i];
        if (tid < Dd) {
            kss[tid] = g_v[bw*Dd + tid];
            b1s[tid] = b1[tid]; b2s[tid] = b2[tid];
            gms[tid] = gamma[tid]; bts[tid] = beta[tid];
        }
    }
    __syncthreads();

    // deg per row (threads 0..63)
    if (tid < 64) {
        float s = 0.0f;
        #pragma unroll 16
        for (int k = 0; k < 64; ++k)
            s += QR[k*QPAD + tid] * kss[k];
        degs[tid] = (s == 0.0f) ? 0.0f : 1.0f / s;
    }
    __syncthreads();

    // GEMM1: u = F @ G
    float acc[4][4];
    #pragma unroll
    for (int i = 0; i < 4; ++i)
        #pragma unroll
        for (int j = 0; j < 4; ++j) acc[i][j] = 0.0f;

    #pragma unroll 8
    for (int k = 0; k < 64; ++k) {
        const float4 a4 = *(const float4*)&QR[k*QPAD + ty*4];
        const float4 b4 = *(const float4*)&Gs[k*Dd + tx*4];
        const float av[4] = {a4.x, a4.y, a4.z, a4.w};
        const float bv[4] = {b4.x, b4.y, b4.z, b4.w};
        #pragma unroll
        for (int i = 0; i < 4; ++i)
            #pragma unroll
            for (int j = 0; j < 4; ++j)
                acc[i][j] += av[i] * bv[j];
    }

    // relu(u/deg + b1) -> registers
    float r[4][4];
    #pragma unroll
    for (int i = 0; i < 4; ++i) {
        const float dinv = degs[ty*4 + i];
        #pragma unroll
        for (int j = 0; j < 4; ++j)
            r[i][j] = fmaxf(acc[i][j] * dinv + b1s[tx*4 + j], 0.0f);
    }
    __syncthreads();   // everyone done reading QR/Gs

    // store R^T into QR, load w2 into Gs
    #pragma unroll
    for (int i = 0; i < 4; ++i)
        #pragma unroll
        for (int j = 0; j < 4; ++j)
            QR[(tx*4 + j)*QPAD + ty*4 + i] = r[i][j];
    {
        const float4* w2b = (const float4*)w2;
        for (int i = tid; i < 1024; i += 256)
            ((float4*)Gs)[i] = w2b[i];
    }
    __syncthreads();

    // GEMM2: h = R @ w2
    #pragma unroll
    for (int i = 0; i < 4; ++i)
        #pragma unroll
        for (int j = 0; j < 4; ++j) acc[i][j] = 0.0f;

    #pragma unroll 8
    for (int k = 0; k < 64; ++k) {
        const float4 a4 = *(const float4*)&QR[k*QPAD + ty*4];
        const float4 b4 = *(const float4*)&Gs[k*Dd + tx*4];
        const float av[4] = {a4.x, a4.y, a4.z, a4.w};
        const float bv[4] = {b4.x, b4.y, b4.z, b4.w};
        #pragma unroll
        for (int i = 0; i < 4; ++i)
            #pragma unroll
            for (int j = 0; j < 4; ++j)
                acc[i][j] += av[i] * bv[j];
    }

    // epilogue: residual + bias, LayerNorm per row (16 threads/row, width-16 shfl)
    float* ob = out + ((size_t)bw * Nn + r0) * Dd;
    #pragma unroll
    for (int i = 0; i < 4; ++i) {
        const int row = ty*4 + i;
        const bool valid = row < nr;
        float4 f4 = make_float4(0.f, 0.f, 0.f, 0.f);
        if (valid) f4 = ((const float4*)fb)[row*16 + tx];
        float h0 = acc[i][0] + f4.x + b2s[tx*4 + 0];
        float h1 = acc[i][1] + f4.y + b2s[tx*4 + 1];
        float h2 = acc[i][2] + f4.z + b2s[tx*4 + 2];
        float h3 = acc[i][3] + f4.w + b2s[tx*4 + 3];

        float s = h0 + h1 + h2 + h3;
        #pragma unroll
        for (int m = 1; m < 16; m <<= 1)
            s += __shfl_xor_sync(0xffffffffu, s, m, 16);
        const float mu = s * (1.0f / 64.0f);

        float a0 = h0 - mu, a1 = h1 - mu, a2 = h2 - mu, a3 = h3 - mu;
        float vs = a0*a0 + a1*a1 + a2*a2 + a3*a3;
        #pragma unroll
        for (int m = 1; m < 16; m <<= 1)
            vs += __shfl_xor_sync(0xffffffffu, vs, m, 16);
        const float rstd = rsqrtf(vs * (1.0f / 64.0f) + 1e-5f);

        if (valid) {
            float4 o;
            o.x = a0 * rstd * gms[tx*4 + 0] + bts[tx*4 + 0];
            o.y = a1 * rstd * gms[tx*4 + 1] + bts[tx*4 + 1];
            o.z = a2 * rstd * gms[tx*4 + 2] + bts[tx*4 + 2];
            o.w = a3 * rstd * gms[tx*4 + 3] + bts[tx*4 + 3];
            ((float4*)ob)[row*16 + tx] = o;
        }
    }
}

extern "C" void kernel_launch(void* const* d_in, const int* in_sizes, int n_in,
                              void* d_out, int out_size) {
    const float* feat    = (const float*)d_in[0];
    const float* weights = (const float*)d_in[1];
    const float* w1      = (const float*)d_in[2];
    const float* b1      = (const float*)d_in[3];
    const float* w2      = (const float*)d_in[4];
    const float* b2      = (const float*)d_in[5];
    const float* gamma   = (const float*)d_in[6];
    const float* beta    = (const float*)d_in[7];
    float* out = (float*)d_out;

    kA<<<BT*5, 256>>>(feat, weights);
    kB<<<BW, 256>>>(w1, weights);
    kC<<<BW*5, 256>>>(feat, b1, w2, b2, gamma, beta, out);
}